// round 13
// baseline (speedup 1.0000x reference)
#include <cuda_runtime.h>
#include <cuda_fp16.h>
#include <math.h>

#define NNODES 50000
#define NEDGES 1600000
#define INCH   128
#define HEADS  4
#define OUTC   128
#define NEG_SLOPE 0.2f
#define SCAN_B 1024

// Scratch (static device globals; no allocation allowed)
__device__ __half2 g_hb[NNODES * OUTC / 2];   // projected features, fp16x2 [N,64]
__device__ float g_as[NNODES * HEADS];        // a_src [N,4]
__device__ float g_ad[NNODES * HEADS];        // a_dst [N,4]
__device__ int   g_cnt[NNODES];               // in-degree (w/o self loop)
__device__ int   g_off[NNODES];               // CSR offsets (exclusive scan)
__device__ int   g_pos[NEDGES];               // rank of edge within its dst bucket
__device__ int   g_csr_src[NEDGES];           // src node per CSR slot
__device__ float g_ew[NEDGES * HEADS];        // exp weights per CSR slot [E,4]

__device__ __forceinline__ float leaky(float v) {
    return v > 0.0f ? v : NEG_SLOPE * v;
}
__device__ __forceinline__ float4 expleaky4(float4 a, float4 b) {
    float4 r;
    r.x = __expf(leaky(a.x + b.x)); r.y = __expf(leaky(a.y + b.y));
    r.z = __expf(leaky(a.z + b.z)); r.w = __expf(leaky(a.w + b.w));
    return r;
}
__device__ __forceinline__ float sel4(float4 v, int h) {
    return h == 0 ? v.x : h == 1 ? v.y : h == 2 ? v.z : v.w;
}

// packed fp32x2 helpers (FFMA2 only reachable via PTX)
__device__ __forceinline__ unsigned long long pack2(float a, float b) {
    unsigned long long r;
    asm("mov.b64 %0, {%1, %2};" : "=l"(r) : "f"(a), "f"(b));
    return r;
}
__device__ __forceinline__ unsigned long long dup2(float a) {
    unsigned long long r;
    asm("mov.b64 %0, {%1, %1};" : "=l"(r) : "f"(a));
    return r;
}
__device__ __forceinline__ void fma2(unsigned long long& d, unsigned long long a,
                                     unsigned long long b) {
    asm("fma.rn.f32x2 %0, %1, %2, %0;" : "+l"(d) : "l"(a), "l"(b));
}
__device__ __forceinline__ void unpack2(unsigned long long v, float& lo, float& hi) {
    asm("mov.b64 {%0, %1}, %2;" : "=f"(lo), "=f"(hi) : "l"(v));
}

// ---------------------------------------------------------------------------
__global__ void k_zero(int N) {
    int i = blockIdx.x * blockDim.x + threadIdx.x;
    if (i < N) g_cnt[i] = 0;
}

// ---------------------------------------------------------------------------
// Projection + logits + fused degree histogram (capturing per-edge rank).
// ---------------------------------------------------------------------------
__global__ void k_proj(const float* __restrict__ x, const float* __restrict__ W,
                       const float* __restrict__ att_s, const float* __restrict__ att_d,
                       const int* __restrict__ ei, int N, int E) {
    __shared__ float xs[64][INCH];  // 32 KB
    int t = threadIdx.x;
    int n0 = blockIdx.x * 64;
    int nvalid = min(64, N - n0);

    for (int i = t * 4; i < 64 * INCH; i += 256 * 4) {
        float4 v = make_float4(0.f, 0.f, 0.f, 0.f);
        if (i < nvalid * INCH) v = *(const float4*)&x[(long long)n0 * INCH + i];
        *(float4*)&xs[0][i] = v;
    }
    __syncthreads();

    int warp = t >> 5;
    int lane = t & 31;
    int nb = warp * 8;

    unsigned long long a01[8], a23[8];
#pragma unroll
    for (int j = 0; j < 8; j++) { a01[j] = 0ull; a23[j] = 0ull; }

#pragma unroll 4
    for (int k = 0; k < INCH; k++) {
        float4 w4 = *(const float4*)&W[k * OUTC + lane * 4];
        unsigned long long w01 = pack2(w4.x, w4.y);
        unsigned long long w23 = pack2(w4.z, w4.w);
#pragma unroll
        for (int j = 0; j < 8; j++) {
            unsigned long long xx = dup2(xs[nb + j][k]);
            fma2(a01[j], w01, xx);
            fma2(a23[j], w23, xx);
        }
    }

    float4 s4 = *(const float4*)&att_s[lane * 4];
    float4 d4 = *(const float4*)&att_d[lane * 4];

#pragma unroll
    for (int j = 0; j < 8; j++) {
        int n = n0 + nb + j;
        float4 acc;
        unpack2(a01[j], acc.x, acc.y);
        unpack2(a23[j], acc.z, acc.w);
        if (n < N) {
            __half2 p0 = __float22half2_rn(make_float2(acc.x, acc.y));
            __half2 p1 = __float22half2_rn(make_float2(acc.z, acc.w));
            uint2 p;
            p.x = *(unsigned int*)&p0;
            p.y = *(unsigned int*)&p1;
            *(uint2*)&g_hb[(long long)n * (OUTC / 2) + lane * 2] = p;
        }

        float vs = acc.x * s4.x + acc.y * s4.y + acc.z * s4.z + acc.w * s4.w;
        float vd = acc.x * d4.x + acc.y * d4.y + acc.z * d4.z + acc.w * d4.w;
#pragma unroll
        for (int o = 4; o > 0; o >>= 1) {
            vs += __shfl_down_sync(0xffffffffu, vs, o);
            vd += __shfl_down_sync(0xffffffffu, vd, o);
        }
        if ((lane & 7) == 0 && n < N) {
            int h = lane >> 3;
            g_as[n * HEADS + h] = vs;
            g_ad[n * HEADS + h] = vd;
        }
    }

    int stride = gridDim.x * 256;
    for (int e = blockIdx.x * 256 + t; e < E; e += stride)
        g_pos[e] = atomicAdd(&g_cnt[ei[E + e]], 1);
}

// ---------------------------------------------------------------------------
// Single-kernel exclusive scan.
// ---------------------------------------------------------------------------
__global__ void k_scan(int N) {
    int t = threadIdx.x;
    int b = blockIdx.x;
    __shared__ int sh[256];

    int pre = b * SCAN_B;
    if (pre > N) pre = N;
    int part = 0;
    for (int i = t; i < pre; i += 256) part += g_cnt[i];
    sh[t] = part;
    __syncthreads();
#pragma unroll
    for (int o = 128; o > 0; o >>= 1) {
        if (t < o) sh[t] += sh[t + o];
        __syncthreads();
    }
    int base = sh[0];
    __syncthreads();

    int i0 = b * SCAN_B + t * 4;
    int v[4];
    int s = 0;
#pragma unroll
    for (int j = 0; j < 4; j++) {
        v[j] = (i0 + j < N) ? g_cnt[i0 + j] : 0;
        s += v[j];
    }
    sh[t] = s;
    __syncthreads();
    for (int o = 1; o < 256; o <<= 1) {
        int u = (t >= o) ? sh[t - o] : 0;
        __syncthreads();
        sh[t] += u;
        __syncthreads();
    }
    int run = base + ((t == 0) ? 0 : sh[t - 1]);
#pragma unroll
    for (int j = 0; j < 4; j++) {
        if (i0 + j < N) g_off[i0 + j] = run;
        run += v[j];
    }
}

// ---------------------------------------------------------------------------
// Scatter + per-edge softmax weight precompute. One edge per thread.
// Latency-heavy random gathers of a_src/a_dst + the exp live HERE (massive
// TLP hides them), so the agg hot loop reads weights coalesced.
// ---------------------------------------------------------------------------
__global__ void k_scatter(const int* __restrict__ ei, int E) {
    int e = blockIdx.x * blockDim.x + threadIdx.x;
    if (e >= E) return;
    int s = ei[e];
    int d = ei[E + e];
    int slot = __ldg(&g_off[d]) + g_pos[e];
    g_csr_src[slot] = s;
    float4 as4 = *(const float4*)&g_as[s * HEADS];
    float4 ad4 = *(const float4*)&g_ad[d * HEADS];
    float4 w = expleaky4(as4, ad4);
    *(float4*)&g_ew[(long long)slot * HEADS] = w;
}

// ---------------------------------------------------------------------------
// Fused softmax + weighted aggregate + bias + ELU. WARP per destination node,
// grid-stride. Weight phase is now a COALESCED LDG.128 of precomputed CSR-
// ordered weights (no random gather, no exp). Feature loop identical to the
// proven round-7 structure.
// ---------------------------------------------------------------------------
__global__ void k_agg(float* __restrict__ out, const float* __restrict__ bias, int N) {
    int warp = threadIdx.x >> 5;  // 8 warps/block
    int lane = threadIdx.x & 31;
    int head = lane >> 3;

    __shared__ float s_w[8][32][HEADS];  // 4 KB

    float4 b4 = *(const float4*)&bias[lane * 4];
    int nstride = gridDim.x * 8;

    for (int d = blockIdx.x * 8 + warp; d < N; d += nstride) {
        int start = g_off[d];
        int deg = g_cnt[d];

        float4 ad4 = *(const float4*)&g_ad[d * HEADS];
        float4 asd = *(const float4*)&g_as[d * HEADS];
        float4 wself = expleaky4(asd, ad4);

        // self-loop
        float4 den = (lane == 0) ? wself : make_float4(0.f, 0.f, 0.f, 0.f);
        float wts = sel4(wself, head);
        const __half2* hrow = &g_hb[(long long)d * (OUTC / 2) + lane * 2];
        float2 f0 = __half22float2(hrow[0]);
        float2 f1 = __half22float2(hrow[1]);
        float4 acc;
        acc.x = wts * f0.x; acc.y = wts * f0.y;
        acc.z = wts * f1.x; acc.w = wts * f1.y;

        for (int base = 0; base < deg; base += 32) {
            int m = min(32, deg - base);
            int s = 0;
            float4 w = make_float4(0.f, 0.f, 0.f, 0.f);
            if (lane < m) {
                int slot = start + base + lane;
                s = g_csr_src[slot];
                w = *(const float4*)&g_ew[(long long)slot * HEADS];  // coalesced
                den.x += w.x; den.y += w.y; den.z += w.z; den.w += w.w;
            }
            *(float4*)&s_w[warp][lane][0] = w;
            __syncwarp();
#pragma unroll 8
            for (int e = 0; e < m; e++) {
                int se = __shfl_sync(0xffffffffu, s, e);
                float wt = s_w[warp][e][head];
                uint2 raw = *(const uint2*)&g_hb[(long long)se * (OUTC / 2) + lane * 2];
                float2 g0 = __half22float2(*(__half2*)&raw.x);
                float2 g1 = __half22float2(*(__half2*)&raw.y);
                acc.x = fmaf(wt, g0.x, acc.x);
                acc.y = fmaf(wt, g0.y, acc.y);
                acc.z = fmaf(wt, g1.x, acc.z);
                acc.w = fmaf(wt, g1.y, acc.w);
            }
            __syncwarp();
        }

        // butterfly reduce denominator
#pragma unroll
        for (int o = 16; o > 0; o >>= 1) {
            den.x += __shfl_xor_sync(0xffffffffu, den.x, o);
            den.y += __shfl_xor_sync(0xffffffffu, den.y, o);
            den.z += __shfl_xor_sync(0xffffffffu, den.z, o);
            den.w += __shfl_xor_sync(0xffffffffu, den.w, o);
        }
        float denv = sel4(den, head) + 1e-16f;

        float4 v;
        v.x = acc.x / denv + b4.x;
        v.y = acc.y / denv + b4.y;
        v.z = acc.z / denv + b4.z;
        v.w = acc.w / denv + b4.w;
        v.x = v.x > 0.f ? v.x : expm1f(v.x);
        v.y = v.y > 0.f ? v.y : expm1f(v.y);
        v.z = v.z > 0.f ? v.z : expm1f(v.z);
        v.w = v.w > 0.f ? v.w : expm1f(v.w);
        *(float4*)&out[(long long)d * OUTC + lane * 4] = v;
    }
}

// ---------------------------------------------------------------------------
extern "C" void kernel_launch(void* const* d_in, const int* in_sizes, int n_in,
                              void* d_out, int out_size) {
    const float* x = (const float*)d_in[0];
    const int* ei = (const int*)d_in[1];   // int32 (jax downcasts int64 w/o x64)
    const float* W = (const float*)d_in[2];
    const float* att_s = (const float*)d_in[3];
    const float* att_d = (const float*)d_in[4];
    const float* bias = (const float*)d_in[5];
    float* out = (float*)d_out;

    int N = in_sizes[0] / INCH;
    int E = in_sizes[1] / 2;
    if (N > NNODES) N = NNODES;
    if (E > NEDGES) E = NEDGES;
    int NB = (N + SCAN_B - 1) / SCAN_B;

    k_zero<<<(N + 255) / 256, 256>>>(N);
    k_proj<<<(N + 63) / 64, 256>>>(x, W, att_s, att_d, ei, N, E);
    k_scan<<<NB, 256>>>(N);
    k_scatter<<<(E + 255) / 256, 256>>>(ei, E);
    int nblk = (N + 7) / 8;
    if (nblk > 2048) nblk = 2048;
    k_agg<<<nblk, 256>>>(out, bias, N);
}

// round 14
// speedup vs baseline: 1.1730x; 1.1730x over previous
#include <cuda_runtime.h>
#include <cuda_fp16.h>
#include <math.h>

#define NNODES 50000
#define NEDGES 1600000
#define INCH   128
#define HEADS  4
#define OUTC   128
#define NEG_SLOPE 0.2f
#define SCAN_B 1024

// Scratch (static device globals; no allocation allowed)
__device__ __half2 g_hb[NNODES * OUTC / 2];   // projected features, fp16x2 [N,64]
__device__ float g_as[NNODES * HEADS];        // a_src [N,4]
__device__ float g_ad[NNODES * HEADS];        // a_dst [N,4]
__device__ int   g_cnt[NNODES];               // in-degree (w/o self loop)
__device__ int   g_off[NNODES];               // CSR offsets (exclusive scan)
__device__ int   g_pos[NEDGES];               // rank of edge within its dst bucket
__device__ int   g_csr_src[NEDGES];           // src node per CSR slot

__device__ __forceinline__ float leaky(float v) {
    return v > 0.0f ? v : NEG_SLOPE * v;
}
__device__ __forceinline__ float4 expleaky4(float4 a, float4 b) {
    float4 r;
    r.x = __expf(leaky(a.x + b.x)); r.y = __expf(leaky(a.y + b.y));
    r.z = __expf(leaky(a.z + b.z)); r.w = __expf(leaky(a.w + b.w));
    return r;
}
__device__ __forceinline__ float sel4(float4 v, int h) {
    return h == 0 ? v.x : h == 1 ? v.y : h == 2 ? v.z : v.w;
}

// packed fp32x2 helpers (FFMA2 only reachable via PTX)
__device__ __forceinline__ unsigned long long pack2(float a, float b) {
    unsigned long long r;
    asm("mov.b64 %0, {%1, %2};" : "=l"(r) : "f"(a), "f"(b));
    return r;
}
__device__ __forceinline__ unsigned long long dup2(float a) {
    unsigned long long r;
    asm("mov.b64 %0, {%1, %1};" : "=l"(r) : "f"(a));
    return r;
}
__device__ __forceinline__ void fma2(unsigned long long& d, unsigned long long a,
                                     unsigned long long b) {
    asm("fma.rn.f32x2 %0, %1, %2, %0;" : "+l"(d) : "l"(a), "l"(b));
}
__device__ __forceinline__ void unpack2(unsigned long long v, float& lo, float& hi) {
    asm("mov.b64 {%0, %1}, %2;" : "=f"(lo), "=f"(hi) : "l"(v));
}

// ---------------------------------------------------------------------------
__global__ void k_zero(int N) {
    int i = blockIdx.x * blockDim.x + threadIdx.x;
    if (i < N) g_cnt[i] = 0;
}

// ---------------------------------------------------------------------------
// Projection + logits + fused degree histogram (capturing per-edge rank).
// Block = 256 threads = 8 warps; each warp computes 8 nodes x 128 cols.
// ---------------------------------------------------------------------------
__global__ void k_proj(const float* __restrict__ x, const float* __restrict__ W,
                       const float* __restrict__ att_s, const float* __restrict__ att_d,
                       const int* __restrict__ ei, int N, int E) {
    __shared__ float xs[64][INCH];  // 32 KB
    int t = threadIdx.x;
    int n0 = blockIdx.x * 64;
    int nvalid = min(64, N - n0);

    for (int i = t * 4; i < 64 * INCH; i += 256 * 4) {
        float4 v = make_float4(0.f, 0.f, 0.f, 0.f);
        if (i < nvalid * INCH) v = *(const float4*)&x[(long long)n0 * INCH + i];
        *(float4*)&xs[0][i] = v;
    }
    __syncthreads();

    int warp = t >> 5;
    int lane = t & 31;
    int nb = warp * 8;

    unsigned long long a01[8], a23[8];
#pragma unroll
    for (int j = 0; j < 8; j++) { a01[j] = 0ull; a23[j] = 0ull; }

#pragma unroll 4
    for (int k = 0; k < INCH; k++) {
        float4 w4 = *(const float4*)&W[k * OUTC + lane * 4];
        unsigned long long w01 = pack2(w4.x, w4.y);
        unsigned long long w23 = pack2(w4.z, w4.w);
#pragma unroll
        for (int j = 0; j < 8; j++) {
            unsigned long long xx = dup2(xs[nb + j][k]);
            fma2(a01[j], w01, xx);
            fma2(a23[j], w23, xx);
        }
    }

    float4 s4 = *(const float4*)&att_s[lane * 4];
    float4 d4 = *(const float4*)&att_d[lane * 4];

#pragma unroll
    for (int j = 0; j < 8; j++) {
        int n = n0 + nb + j;
        float4 acc;
        unpack2(a01[j], acc.x, acc.y);
        unpack2(a23[j], acc.z, acc.w);
        if (n < N) {
            __half2 p0 = __float22half2_rn(make_float2(acc.x, acc.y));
            __half2 p1 = __float22half2_rn(make_float2(acc.z, acc.w));
            uint2 p;
            p.x = *(unsigned int*)&p0;
            p.y = *(unsigned int*)&p1;
            *(uint2*)&g_hb[(long long)n * (OUTC / 2) + lane * 2] = p;
        }

        float vs = acc.x * s4.x + acc.y * s4.y + acc.z * s4.z + acc.w * s4.w;
        float vd = acc.x * d4.x + acc.y * d4.y + acc.z * d4.z + acc.w * d4.w;
#pragma unroll
        for (int o = 4; o > 0; o >>= 1) {
            vs += __shfl_down_sync(0xffffffffu, vs, o);
            vd += __shfl_down_sync(0xffffffffu, vd, o);
        }
        if ((lane & 7) == 0 && n < N) {
            int h = lane >> 3;
            g_as[n * HEADS + h] = vs;
            g_ad[n * HEADS + h] = vd;
        }
    }

    // fused degree histogram; atomic return value = edge's rank in its bucket
    int stride = gridDim.x * 256;
    for (int e = blockIdx.x * 256 + t; e < E; e += stride)
        g_pos[e] = atomicAdd(&g_cnt[ei[E + e]], 1);
}

// ---------------------------------------------------------------------------
// Single-kernel exclusive scan: each block recomputes its base by striding
// over the preceding g_cnt range, then local prefix.
// ---------------------------------------------------------------------------
__global__ void k_scan(int N) {
    int t = threadIdx.x;
    int b = blockIdx.x;
    __shared__ int sh[256];

    int pre = b * SCAN_B;
    if (pre > N) pre = N;
    int part = 0;
    for (int i = t; i < pre; i += 256) part += g_cnt[i];
    sh[t] = part;
    __syncthreads();
#pragma unroll
    for (int o = 128; o > 0; o >>= 1) {
        if (t < o) sh[t] += sh[t + o];
        __syncthreads();
    }
    int base = sh[0];
    __syncthreads();

    int i0 = b * SCAN_B + t * 4;
    int v[4];
    int s = 0;
#pragma unroll
    for (int j = 0; j < 4; j++) {
        v[j] = (i0 + j < N) ? g_cnt[i0 + j] : 0;
        s += v[j];
    }
    sh[t] = s;
    __syncthreads();
    for (int o = 1; o < 256; o <<= 1) {
        int u = (t >= o) ? sh[t - o] : 0;
        __syncthreads();
        sh[t] += u;
        __syncthreads();
    }
    int run = base + ((t == 0) ? 0 : sh[t - 1]);
#pragma unroll
    for (int j = 0; j < 4; j++) {
        if (i0 + j < N) g_off[i0 + j] = run;
        run += v[j];
    }
}

// ---------------------------------------------------------------------------
// Atomic-free scatter, 2 edges per thread (int2 loads on both rows).
// ---------------------------------------------------------------------------
__global__ void k_scatter(const int* __restrict__ ei, int E) {
    int i = blockIdx.x * blockDim.x + threadIdx.x;
    int e = i * 2;
    if (e + 1 < E) {
        int2 s2 = *(const int2*)&ei[e];
        int2 d2 = *(const int2*)&ei[E + e];
        int2 p2 = *(const int2*)&g_pos[e];
        g_csr_src[__ldg(&g_off[d2.x]) + p2.x] = s2.x;
        g_csr_src[__ldg(&g_off[d2.y]) + p2.y] = s2.y;
    } else if (e < E) {
        int s = ei[e];
        int d = ei[E + e];
        g_csr_src[__ldg(&g_off[d]) + g_pos[e]] = s;
    }
}

// ---------------------------------------------------------------------------
// Fused softmax + weighted aggregate + bias + ELU. WARP per destination node,
// grid-stride over nodes for load balance. Features gathered as fp16x2
// (LDG.64/lane); weights via per-warp smem tile; denominator via butterfly
// reduce. No block syncs, no atomics, NO writes to shared metadata.
// __launch_bounds__(256, 6): regs 48->42 so 6 blocks/SM resident (occupancy
// 52% -> 75%) — this kernel is latency-bound (issue 24%, mem pipes idle).
// ---------------------------------------------------------------------------
__global__ void __launch_bounds__(256, 6)
k_agg(float* __restrict__ out, const float* __restrict__ bias, int N) {
    int warp = threadIdx.x >> 5;  // 8 warps/block
    int lane = threadIdx.x & 31;
    int head = lane >> 3;

    __shared__ float s_w[8][32][HEADS];  // 4 KB

    float4 b4 = *(const float4*)&bias[lane * 4];
    int nstride = gridDim.x * 8;

    for (int d = blockIdx.x * 8 + warp; d < N; d += nstride) {
        int start = g_off[d];
        int deg = g_cnt[d];

        float4 ad4 = *(const float4*)&g_ad[d * HEADS];
        float4 asd = *(const float4*)&g_as[d * HEADS];
        float4 wself = expleaky4(asd, ad4);

        // self-loop
        float4 den = (lane == 0) ? wself : make_float4(0.f, 0.f, 0.f, 0.f);
        float wts = sel4(wself, head);
        const __half2* hrow = &g_hb[(long long)d * (OUTC / 2) + lane * 2];
        float2 f0 = __half22float2(hrow[0]);
        float2 f1 = __half22float2(hrow[1]);
        float4 acc;
        acc.x = wts * f0.x; acc.y = wts * f0.y;
        acc.z = wts * f1.x; acc.w = wts * f1.y;

        for (int base = 0; base < deg; base += 32) {
            int m = min(32, deg - base);
            int s = 0;
            float4 w = make_float4(0.f, 0.f, 0.f, 0.f);
            if (lane < m) {
                s = g_csr_src[start + base + lane];
                float4 as4 = *(const float4*)&g_as[s * HEADS];
                w = expleaky4(as4, ad4);
                den.x += w.x; den.y += w.y; den.z += w.z; den.w += w.w;
            }
            *(float4*)&s_w[warp][lane][0] = w;
            __syncwarp();
#pragma unroll 8
            for (int e = 0; e < m; e++) {
                int se = __shfl_sync(0xffffffffu, s, e);
                float wt = s_w[warp][e][head];
                uint2 raw = *(const uint2*)&g_hb[(long long)se * (OUTC / 2) + lane * 2];
                float2 g0 = __half22float2(*(__half2*)&raw.x);
                float2 g1 = __half22float2(*(__half2*)&raw.y);
                acc.x = fmaf(wt, g0.x, acc.x);
                acc.y = fmaf(wt, g0.y, acc.y);
                acc.z = fmaf(wt, g1.x, acc.z);
                acc.w = fmaf(wt, g1.y, acc.w);
            }
            __syncwarp();
        }

        // butterfly reduce denominator
#pragma unroll
        for (int o = 16; o > 0; o >>= 1) {
            den.x += __shfl_xor_sync(0xffffffffu, den.x, o);
            den.y += __shfl_xor_sync(0xffffffffu, den.y, o);
            den.z += __shfl_xor_sync(0xffffffffu, den.z, o);
            den.w += __shfl_xor_sync(0xffffffffu, den.w, o);
        }
        float denv = sel4(den, head) + 1e-16f;

        float4 v;
        v.x = acc.x / denv + b4.x;
        v.y = acc.y / denv + b4.y;
        v.z = acc.z / denv + b4.z;
        v.w = acc.w / denv + b4.w;
        v.x = v.x > 0.f ? v.x : expm1f(v.x);
        v.y = v.y > 0.f ? v.y : expm1f(v.y);
        v.z = v.z > 0.f ? v.z : expm1f(v.z);
        v.w = v.w > 0.f ? v.w : expm1f(v.w);
        *(float4*)&out[(long long)d * OUTC + lane * 4] = v;
    }
}

// ---------------------------------------------------------------------------
extern "C" void kernel_launch(void* const* d_in, const int* in_sizes, int n_in,
                              void* d_out, int out_size) {
    const float* x = (const float*)d_in[0];
    const int* ei = (const int*)d_in[1];   // int32 (jax downcasts int64 w/o x64)
    const float* W = (const float*)d_in[2];
    const float* att_s = (const float*)d_in[3];
    const float* att_d = (const float*)d_in[4];
    const float* bias = (const float*)d_in[5];
    float* out = (float*)d_out;

    int N = in_sizes[0] / INCH;
    int E = in_sizes[1] / 2;
    if (N > NNODES) N = NNODES;
    if (E > NEDGES) E = NEDGES;
    int NB = (N + SCAN_B - 1) / SCAN_B;

    k_zero<<<(N + 255) / 256, 256>>>(N);
    k_proj<<<(N + 63) / 64, 256>>>(x, W, att_s, att_d, ei, N, E);
    k_scan<<<NB, 256>>>(N);
    {
        int half = (E + 1) / 2;
        k_scatter<<<(half + 255) / 256, 256>>>(ei, E);
    }
    int nblk = (N + 7) / 8;
    if (nblk > 2048) nblk = 2048;
    k_agg<<<nblk, 256>>>(out, bias, N);
}

// round 15
// speedup vs baseline: 1.3597x; 1.1592x over previous
#include <cuda_runtime.h>
#include <cuda_fp16.h>
#include <math.h>

#define NNODES 50000
#define NEDGES 1600000
#define INCH   128
#define HEADS  4
#define OUTC   128
#define NEG_SLOPE 0.2f
#define SCAN_B 1024

// Scratch (static device globals; no allocation allowed)
__device__ __half2 g_hb[NNODES * OUTC / 2];   // projected features, fp16x2 [N,64]
__device__ float g_as[NNODES * HEADS];        // a_src [N,4]
__device__ float g_ad[NNODES * HEADS];        // a_dst [N,4]
__device__ int   g_cnt[NNODES];               // in-degree (w/o self loop)
__device__ int   g_off[NNODES];               // CSR offsets (exclusive scan)
__device__ int   g_pos[NEDGES];               // rank of edge within its dst bucket
__device__ int   g_csr_src[NEDGES];           // src node per CSR slot

__device__ __forceinline__ float leaky(float v) {
    return v > 0.0f ? v : NEG_SLOPE * v;
}
__device__ __forceinline__ float4 expleaky4(float4 a, float4 b) {
    float4 r;
    r.x = __expf(leaky(a.x + b.x)); r.y = __expf(leaky(a.y + b.y));
    r.z = __expf(leaky(a.z + b.z)); r.w = __expf(leaky(a.w + b.w));
    return r;
}
__device__ __forceinline__ float sel4(float4 v, int h) {
    return h == 0 ? v.x : h == 1 ? v.y : h == 2 ? v.z : v.w;
}

// packed fp32x2 helpers (FFMA2 only reachable via PTX)
__device__ __forceinline__ unsigned long long pack2(float a, float b) {
    unsigned long long r;
    asm("mov.b64 %0, {%1, %2};" : "=l"(r) : "f"(a), "f"(b));
    return r;
}
__device__ __forceinline__ unsigned long long dup2(float a) {
    unsigned long long r;
    asm("mov.b64 %0, {%1, %1};" : "=l"(r) : "f"(a));
    return r;
}
__device__ __forceinline__ void fma2(unsigned long long& d, unsigned long long a,
                                     unsigned long long b) {
    asm("fma.rn.f32x2 %0, %1, %2, %0;" : "+l"(d) : "l"(a), "l"(b));
}
__device__ __forceinline__ void unpack2(unsigned long long v, float& lo, float& hi) {
    asm("mov.b64 {%0, %1}, %2;" : "=f"(lo), "=f"(hi) : "l"(v));
}

// ---------------------------------------------------------------------------
__global__ void k_zero(int N) {
    int i = blockIdx.x * blockDim.x + threadIdx.x;
    if (i < N) g_cnt[i] = 0;
}

// ---------------------------------------------------------------------------
// Projection + logits + fused degree histogram (capturing per-edge rank).
// Block = 256 threads = 8 warps; each warp computes 8 nodes x 128 cols.
// ---------------------------------------------------------------------------
__global__ void k_proj(const float* __restrict__ x, const float* __restrict__ W,
                       const float* __restrict__ att_s, const float* __restrict__ att_d,
                       const int* __restrict__ ei, int N, int E) {
    __shared__ float xs[64][INCH];  // 32 KB
    int t = threadIdx.x;
    int n0 = blockIdx.x * 64;
    int nvalid = min(64, N - n0);

    for (int i = t * 4; i < 64 * INCH; i += 256 * 4) {
        float4 v = make_float4(0.f, 0.f, 0.f, 0.f);
        if (i < nvalid * INCH) v = *(const float4*)&x[(long long)n0 * INCH + i];
        *(float4*)&xs[0][i] = v;
    }
    __syncthreads();

    int warp = t >> 5;
    int lane = t & 31;
    int nb = warp * 8;

    unsigned long long a01[8], a23[8];
#pragma unroll
    for (int j = 0; j < 8; j++) { a01[j] = 0ull; a23[j] = 0ull; }

#pragma unroll 4
    for (int k = 0; k < INCH; k++) {
        float4 w4 = *(const float4*)&W[k * OUTC + lane * 4];
        unsigned long long w01 = pack2(w4.x, w4.y);
        unsigned long long w23 = pack2(w4.z, w4.w);
#pragma unroll
        for (int j = 0; j < 8; j++) {
            unsigned long long xx = dup2(xs[nb + j][k]);
            fma2(a01[j], w01, xx);
            fma2(a23[j], w23, xx);
        }
    }

    float4 s4 = *(const float4*)&att_s[lane * 4];
    float4 d4 = *(const float4*)&att_d[lane * 4];

#pragma unroll
    for (int j = 0; j < 8; j++) {
        int n = n0 + nb + j;
        float4 acc;
        unpack2(a01[j], acc.x, acc.y);
        unpack2(a23[j], acc.z, acc.w);
        if (n < N) {
            __half2 p0 = __float22half2_rn(make_float2(acc.x, acc.y));
            __half2 p1 = __float22half2_rn(make_float2(acc.z, acc.w));
            uint2 p;
            p.x = *(unsigned int*)&p0;
            p.y = *(unsigned int*)&p1;
            *(uint2*)&g_hb[(long long)n * (OUTC / 2) + lane * 2] = p;
        }

        float vs = acc.x * s4.x + acc.y * s4.y + acc.z * s4.z + acc.w * s4.w;
        float vd = acc.x * d4.x + acc.y * d4.y + acc.z * d4.z + acc.w * d4.w;
#pragma unroll
        for (int o = 4; o > 0; o >>= 1) {
            vs += __shfl_down_sync(0xffffffffu, vs, o);
            vd += __shfl_down_sync(0xffffffffu, vd, o);
        }
        if ((lane & 7) == 0 && n < N) {
            int h = lane >> 3;
            g_as[n * HEADS + h] = vs;
            g_ad[n * HEADS + h] = vd;
        }
    }

    // fused degree histogram; atomic return value = edge's rank in its bucket
    int stride = gridDim.x * 256;
    for (int e = blockIdx.x * 256 + t; e < E; e += stride)
        g_pos[e] = atomicAdd(&g_cnt[ei[E + e]], 1);
}

// ---------------------------------------------------------------------------
// Single-kernel exclusive scan: each block recomputes its base by striding
// over the preceding g_cnt range, then local prefix.
// ---------------------------------------------------------------------------
__global__ void k_scan(int N) {
    int t = threadIdx.x;
    int b = blockIdx.x;
    __shared__ int sh[256];

    int pre = b * SCAN_B;
    if (pre > N) pre = N;
    int part = 0;
    for (int i = t; i < pre; i += 256) part += g_cnt[i];
    sh[t] = part;
    __syncthreads();
#pragma unroll
    for (int o = 128; o > 0; o >>= 1) {
        if (t < o) sh[t] += sh[t + o];
        __syncthreads();
    }
    int base = sh[0];
    __syncthreads();

    int i0 = b * SCAN_B + t * 4;
    int v[4];
    int s = 0;
#pragma unroll
    for (int j = 0; j < 4; j++) {
        v[j] = (i0 + j < N) ? g_cnt[i0 + j] : 0;
        s += v[j];
    }
    sh[t] = s;
    __syncthreads();
    for (int o = 1; o < 256; o <<= 1) {
        int u = (t >= o) ? sh[t - o] : 0;
        __syncthreads();
        sh[t] += u;
        __syncthreads();
    }
    int run = base + ((t == 0) ? 0 : sh[t - 1]);
#pragma unroll
    for (int j = 0; j < 4; j++) {
        if (i0 + j < N) g_off[i0 + j] = run;
        run += v[j];
    }
}

// ---------------------------------------------------------------------------
// Atomic-free scatter, 2 edges per thread (int2 loads on both rows).
// ---------------------------------------------------------------------------
__global__ void k_scatter(const int* __restrict__ ei, int E) {
    int i = blockIdx.x * blockDim.x + threadIdx.x;
    int e = i * 2;
    if (e + 1 < E) {
        int2 s2 = *(const int2*)&ei[e];
        int2 d2 = *(const int2*)&ei[E + e];
        int2 p2 = *(const int2*)&g_pos[e];
        g_csr_src[__ldg(&g_off[d2.x]) + p2.x] = s2.x;
        g_csr_src[__ldg(&g_off[d2.y]) + p2.y] = s2.y;
    } else if (e < E) {
        int s = ei[e];
        int d = ei[E + e];
        g_csr_src[__ldg(&g_off[d]) + g_pos[e]] = s;
    }
}

// ---------------------------------------------------------------------------
// Fused softmax + weighted aggregate + bias + ELU. WARP per destination node,
// grid-stride over nodes for load balance. Features gathered as fp16x2
// (LDG.64/lane); weights via per-warp smem tile; denominator via butterfly
// reduce. No block syncs, no atomics, no launch_bounds reg cap (spills hurt).
// Block = 128 threads (4 warps): same 40-warp/SM occupancy at regs=48, but
// half-size scheduling quanta -> smaller tail-wave imbalance.
// ---------------------------------------------------------------------------
__global__ void k_agg(float* __restrict__ out, const float* __restrict__ bias, int N) {
    int warp = threadIdx.x >> 5;  // 4 warps/block
    int lane = threadIdx.x & 31;
    int head = lane >> 3;

    __shared__ float s_w[4][32][HEADS];  // 2 KB

    float4 b4 = *(const float4*)&bias[lane * 4];
    int nstride = gridDim.x * 4;

    for (int d = blockIdx.x * 4 + warp; d < N; d += nstride) {
        int start = g_off[d];
        int deg = g_cnt[d];

        float4 ad4 = *(const float4*)&g_ad[d * HEADS];
        float4 asd = *(const float4*)&g_as[d * HEADS];
        float4 wself = expleaky4(asd, ad4);

        // self-loop
        float4 den = (lane == 0) ? wself : make_float4(0.f, 0.f, 0.f, 0.f);
        float wts = sel4(wself, head);
        const __half2* hrow = &g_hb[(long long)d * (OUTC / 2) + lane * 2];
        float2 f0 = __half22float2(hrow[0]);
        float2 f1 = __half22float2(hrow[1]);
        float4 acc;
        acc.x = wts * f0.x; acc.y = wts * f0.y;
        acc.z = wts * f1.x; acc.w = wts * f1.y;

        for (int base = 0; base < deg; base += 32) {
            int m = min(32, deg - base);
            int s = 0;
            float4 w = make_float4(0.f, 0.f, 0.f, 0.f);
            if (lane < m) {
                s = g_csr_src[start + base + lane];
                float4 as4 = *(const float4*)&g_as[s * HEADS];
                w = expleaky4(as4, ad4);
                den.x += w.x; den.y += w.y; den.z += w.z; den.w += w.w;
            }
            *(float4*)&s_w[warp][lane][0] = w;
            __syncwarp();
#pragma unroll 8
            for (int e = 0; e < m; e++) {
                int se = __shfl_sync(0xffffffffu, s, e);
                float wt = s_w[warp][e][head];
                uint2 raw = *(const uint2*)&g_hb[(long long)se * (OUTC / 2) + lane * 2];
                float2 g0 = __half22float2(*(__half2*)&raw.x);
                float2 g1 = __half22float2(*(__half2*)&raw.y);
                acc.x = fmaf(wt, g0.x, acc.x);
                acc.y = fmaf(wt, g0.y, acc.y);
                acc.z = fmaf(wt, g1.x, acc.z);
                acc.w = fmaf(wt, g1.y, acc.w);
            }
            __syncwarp();
        }

        // butterfly reduce denominator
#pragma unroll
        for (int o = 16; o > 0; o >>= 1) {
            den.x += __shfl_xor_sync(0xffffffffu, den.x, o);
            den.y += __shfl_xor_sync(0xffffffffu, den.y, o);
            den.z += __shfl_xor_sync(0xffffffffu, den.z, o);
            den.w += __shfl_xor_sync(0xffffffffu, den.w, o);
        }
        float denv = sel4(den, head) + 1e-16f;

        float4 v;
        v.x = acc.x / denv + b4.x;
        v.y = acc.y / denv + b4.y;
        v.z = acc.z / denv + b4.z;
        v.w = acc.w / denv + b4.w;
        v.x = v.x > 0.f ? v.x : expm1f(v.x);
        v.y = v.y > 0.f ? v.y : expm1f(v.y);
        v.z = v.z > 0.f ? v.z : expm1f(v.z);
        v.w = v.w > 0.f ? v.w : expm1f(v.w);
        *(float4*)&out[(long long)d * OUTC + lane * 4] = v;
    }
}

// ---------------------------------------------------------------------------
extern "C" void kernel_launch(void* const* d_in, const int* in_sizes, int n_in,
                              void* d_out, int out_size) {
    const float* x = (const float*)d_in[0];
    const int* ei = (const int*)d_in[1];   // int32 (jax downcasts int64 w/o x64)
    const float* W = (const float*)d_in[2];
    const float* att_s = (const float*)d_in[3];
    const float* att_d = (const float*)d_in[4];
    const float* bias = (const float*)d_in[5];
    float* out = (float*)d_out;

    int N = in_sizes[0] / INCH;
    int E = in_sizes[1] / 2;
    if (N > NNODES) N = NNODES;
    if (E > NEDGES) E = NEDGES;
    int NB = (N + SCAN_B - 1) / SCAN_B;

    k_zero<<<(N + 255) / 256, 256>>>(N);
    k_proj<<<(N + 63) / 64, 256>>>(x, W, att_s, att_d, ei, N, E);
    k_scan<<<NB, 256>>>(N);
    {
        int half = (E + 1) / 2;
        k_scatter<<<(half + 255) / 256, 256>>>(ei, E);
    }
    int nblk = (N + 3) / 4;
    if (nblk > 4096) nblk = 4096;
    k_agg<<<nblk, 128>>>(out, bias, N);
}

// round 16
// speedup vs baseline: 1.4852x; 1.0923x over previous
#include <cuda_runtime.h>
#include <cuda_fp16.h>
#include <math.h>

#define NNODES 50000
#define NEDGES 1600000
#define INCH   128
#define HEADS  4
#define OUTC   128
#define NEG_SLOPE 0.2f
#define SCAN_B 1024

// Scratch (static device globals; no allocation allowed)
__device__ __half2 g_hb[NNODES * OUTC / 2];   // projected features, fp16x2 [N,64]
__device__ float g_as[NNODES * HEADS];        // a_src [N,4]
__device__ float g_ad[NNODES * HEADS];        // a_dst [N,4]
__device__ int   g_cnt[NNODES];               // in-degree (w/o self loop)
__device__ int   g_off[NNODES];               // CSR offsets (exclusive scan)
__device__ int   g_pos[NEDGES];               // rank of edge within its dst bucket
__device__ int   g_csr_src[NEDGES];           // src node per CSR slot

__device__ __forceinline__ float leaky(float v) {
    return v > 0.0f ? v : NEG_SLOPE * v;
}
__device__ __forceinline__ float4 expleaky4(float4 a, float4 b) {
    float4 r;
    r.x = __expf(leaky(a.x + b.x)); r.y = __expf(leaky(a.y + b.y));
    r.z = __expf(leaky(a.z + b.z)); r.w = __expf(leaky(a.w + b.w));
    return r;
}
__device__ __forceinline__ float sel4(float4 v, int h) {
    return h == 0 ? v.x : h == 1 ? v.y : h == 2 ? v.z : v.w;
}

// packed fp32x2 helpers (FFMA2 only reachable via PTX)
__device__ __forceinline__ unsigned long long pack2(float a, float b) {
    unsigned long long r;
    asm("mov.b64 %0, {%1, %2};" : "=l"(r) : "f"(a), "f"(b));
    return r;
}
__device__ __forceinline__ unsigned long long dup2(float a) {
    unsigned long long r;
    asm("mov.b64 %0, {%1, %1};" : "=l"(r) : "f"(a));
    return r;
}
__device__ __forceinline__ void fma2(unsigned long long& d, unsigned long long a,
                                     unsigned long long b) {
    asm("fma.rn.f32x2 %0, %1, %2, %0;" : "+l"(d) : "l"(a), "l"(b));
}
__device__ __forceinline__ void unpack2(unsigned long long v, float& lo, float& hi) {
    asm("mov.b64 {%0, %1}, %2;" : "=f"(lo), "=f"(hi) : "l"(v));
}

// ---------------------------------------------------------------------------
__global__ void k_zero(int N) {
    int i = blockIdx.x * blockDim.x + threadIdx.x;
    if (i < N) g_cnt[i] = 0;
}

// ---------------------------------------------------------------------------
// Degree histogram; atomic return value = edge's rank in its dst bucket.
// ---------------------------------------------------------------------------
__global__ void k_hist(const int* __restrict__ ei, int E) {
    int e = blockIdx.x * blockDim.x + threadIdx.x;
    if (e < E) g_pos[e] = atomicAdd(&g_cnt[ei[E + e]], 1);
}

// ---------------------------------------------------------------------------
// Projection + logits (GEMM only; histogram split out for stream overlap).
// Block = 256 threads = 8 warps; each warp computes 8 nodes x 128 cols.
// ---------------------------------------------------------------------------
__global__ void k_proj(const float* __restrict__ x, const float* __restrict__ W,
                       const float* __restrict__ att_s, const float* __restrict__ att_d,
                       int N) {
    __shared__ float xs[64][INCH];  // 32 KB
    int t = threadIdx.x;
    int n0 = blockIdx.x * 64;
    int nvalid = min(64, N - n0);

    for (int i = t * 4; i < 64 * INCH; i += 256 * 4) {
        float4 v = make_float4(0.f, 0.f, 0.f, 0.f);
        if (i < nvalid * INCH) v = *(const float4*)&x[(long long)n0 * INCH + i];
        *(float4*)&xs[0][i] = v;
    }
    __syncthreads();

    int warp = t >> 5;
    int lane = t & 31;
    int nb = warp * 8;

    unsigned long long a01[8], a23[8];
#pragma unroll
    for (int j = 0; j < 8; j++) { a01[j] = 0ull; a23[j] = 0ull; }

#pragma unroll 4
    for (int k = 0; k < INCH; k++) {
        float4 w4 = *(const float4*)&W[k * OUTC + lane * 4];
        unsigned long long w01 = pack2(w4.x, w4.y);
        unsigned long long w23 = pack2(w4.z, w4.w);
#pragma unroll
        for (int j = 0; j < 8; j++) {
            unsigned long long xx = dup2(xs[nb + j][k]);
            fma2(a01[j], w01, xx);
            fma2(a23[j], w23, xx);
        }
    }

    float4 s4 = *(const float4*)&att_s[lane * 4];
    float4 d4 = *(const float4*)&att_d[lane * 4];

#pragma unroll
    for (int j = 0; j < 8; j++) {
        int n = n0 + nb + j;
        float4 acc;
        unpack2(a01[j], acc.x, acc.y);
        unpack2(a23[j], acc.z, acc.w);
        if (n < N) {
            __half2 p0 = __float22half2_rn(make_float2(acc.x, acc.y));
            __half2 p1 = __float22half2_rn(make_float2(acc.z, acc.w));
            uint2 p;
            p.x = *(unsigned int*)&p0;
            p.y = *(unsigned int*)&p1;
            *(uint2*)&g_hb[(long long)n * (OUTC / 2) + lane * 2] = p;
        }

        float vs = acc.x * s4.x + acc.y * s4.y + acc.z * s4.z + acc.w * s4.w;
        float vd = acc.x * d4.x + acc.y * d4.y + acc.z * d4.z + acc.w * d4.w;
#pragma unroll
        for (int o = 4; o > 0; o >>= 1) {
            vs += __shfl_down_sync(0xffffffffu, vs, o);
            vd += __shfl_down_sync(0xffffffffu, vd, o);
        }
        if ((lane & 7) == 0 && n < N) {
            int h = lane >> 3;
            g_as[n * HEADS + h] = vs;
            g_ad[n * HEADS + h] = vd;
        }
    }
}

// ---------------------------------------------------------------------------
// Single-kernel exclusive scan.
// ---------------------------------------------------------------------------
__global__ void k_scan(int N) {
    int t = threadIdx.x;
    int b = blockIdx.x;
    __shared__ int sh[256];

    int pre = b * SCAN_B;
    if (pre > N) pre = N;
    int part = 0;
    for (int i = t; i < pre; i += 256) part += g_cnt[i];
    sh[t] = part;
    __syncthreads();
#pragma unroll
    for (int o = 128; o > 0; o >>= 1) {
        if (t < o) sh[t] += sh[t + o];
        __syncthreads();
    }
    int base = sh[0];
    __syncthreads();

    int i0 = b * SCAN_B + t * 4;
    int v[4];
    int s = 0;
#pragma unroll
    for (int j = 0; j < 4; j++) {
        v[j] = (i0 + j < N) ? g_cnt[i0 + j] : 0;
        s += v[j];
    }
    sh[t] = s;
    __syncthreads();
    for (int o = 1; o < 256; o <<= 1) {
        int u = (t >= o) ? sh[t - o] : 0;
        __syncthreads();
        sh[t] += u;
        __syncthreads();
    }
    int run = base + ((t == 0) ? 0 : sh[t - 1]);
#pragma unroll
    for (int j = 0; j < 4; j++) {
        if (i0 + j < N) g_off[i0 + j] = run;
        run += v[j];
    }
}

// ---------------------------------------------------------------------------
// Atomic-free scatter, 2 edges per thread (int2 loads on both rows).
// ---------------------------------------------------------------------------
__global__ void k_scatter(const int* __restrict__ ei, int E) {
    int i = blockIdx.x * blockDim.x + threadIdx.x;
    int e = i * 2;
    if (e + 1 < E) {
        int2 s2 = *(const int2*)&ei[e];
        int2 d2 = *(const int2*)&ei[E + e];
        int2 p2 = *(const int2*)&g_pos[e];
        g_csr_src[__ldg(&g_off[d2.x]) + p2.x] = s2.x;
        g_csr_src[__ldg(&g_off[d2.y]) + p2.y] = s2.y;
    } else if (e < E) {
        int s = ei[e];
        int d = ei[E + e];
        g_csr_src[__ldg(&g_off[d]) + g_pos[e]] = s;
    }
}

// ---------------------------------------------------------------------------
// Fused softmax + weighted aggregate + bias + ELU. WARP per destination node,
// grid-stride over nodes for load balance. Block = 128 threads (4 warps).
// Structure locked at the proven round-14 configuration.
// ---------------------------------------------------------------------------
__global__ void k_agg(float* __restrict__ out, const float* __restrict__ bias, int N) {
    int warp = threadIdx.x >> 5;  // 4 warps/block
    int lane = threadIdx.x & 31;
    int head = lane >> 3;

    __shared__ float s_w[4][32][HEADS];  // 2 KB

    float4 b4 = *(const float4*)&bias[lane * 4];
    int nstride = gridDim.x * 4;

    for (int d = blockIdx.x * 4 + warp; d < N; d += nstride) {
        int start = g_off[d];
        int deg = g_cnt[d];

        float4 ad4 = *(const float4*)&g_ad[d * HEADS];
        float4 asd = *(const float4*)&g_as[d * HEADS];
        float4 wself = expleaky4(asd, ad4);

        // self-loop
        float4 den = (lane == 0) ? wself : make_float4(0.f, 0.f, 0.f, 0.f);
        float wts = sel4(wself, head);
        const __half2* hrow = &g_hb[(long long)d * (OUTC / 2) + lane * 2];
        float2 f0 = __half22float2(hrow[0]);
        float2 f1 = __half22float2(hrow[1]);
        float4 acc;
        acc.x = wts * f0.x; acc.y = wts * f0.y;
        acc.z = wts * f1.x; acc.w = wts * f1.y;

        for (int base = 0; base < deg; base += 32) {
            int m = min(32, deg - base);
            int s = 0;
            float4 w = make_float4(0.f, 0.f, 0.f, 0.f);
            if (lane < m) {
                s = g_csr_src[start + base + lane];
                float4 as4 = *(const float4*)&g_as[s * HEADS];
                w = expleaky4(as4, ad4);
                den.x += w.x; den.y += w.y; den.z += w.z; den.w += w.w;
            }
            *(float4*)&s_w[warp][lane][0] = w;
            __syncwarp();
#pragma unroll 8
            for (int e = 0; e < m; e++) {
                int se = __shfl_sync(0xffffffffu, s, e);
                float wt = s_w[warp][e][head];
                uint2 raw = *(const uint2*)&g_hb[(long long)se * (OUTC / 2) + lane * 2];
                float2 g0 = __half22float2(*(__half2*)&raw.x);
                float2 g1 = __half22float2(*(__half2*)&raw.y);
                acc.x = fmaf(wt, g0.x, acc.x);
                acc.y = fmaf(wt, g0.y, acc.y);
                acc.z = fmaf(wt, g1.x, acc.z);
                acc.w = fmaf(wt, g1.y, acc.w);
            }
            __syncwarp();
        }

        // butterfly reduce denominator
#pragma unroll
        for (int o = 16; o > 0; o >>= 1) {
            den.x += __shfl_xor_sync(0xffffffffu, den.x, o);
            den.y += __shfl_xor_sync(0xffffffffu, den.y, o);
            den.z += __shfl_xor_sync(0xffffffffu, den.z, o);
            den.w += __shfl_xor_sync(0xffffffffu, den.w, o);
        }
        float denv = sel4(den, head) + 1e-16f;

        float4 v;
        v.x = acc.x / denv + b4.x;
        v.y = acc.y / denv + b4.y;
        v.z = acc.z / denv + b4.z;
        v.w = acc.w / denv + b4.w;
        v.x = v.x > 0.f ? v.x : expm1f(v.x);
        v.y = v.y > 0.f ? v.y : expm1f(v.y);
        v.z = v.z > 0.f ? v.z : expm1f(v.z);
        v.w = v.w > 0.f ? v.w : expm1f(v.w);
        *(float4*)&out[(long long)d * OUTC + lane * 4] = v;
    }
}

// ---------------------------------------------------------------------------
// Launch DAG (graph-capture fork/join):
//   main:  zero ─┬─ proj(GEMM) ──────────────┬─ agg
//   aux:         └─ hist → scan → scatter ───┘
// Streams/events created lazily on the first (non-captured) correctness call;
// during capture only launches + event record/wait are issued.
// ---------------------------------------------------------------------------
extern "C" void kernel_launch(void* const* d_in, const int* in_sizes, int n_in,
                              void* d_out, int out_size) {
    const float* x = (const float*)d_in[0];
    const int* ei = (const int*)d_in[1];   // int32 (jax downcasts int64 w/o x64)
    const float* W = (const float*)d_in[2];
    const float* att_s = (const float*)d_in[3];
    const float* att_d = (const float*)d_in[4];
    const float* bias = (const float*)d_in[5];
    float* out = (float*)d_out;

    int N = in_sizes[0] / INCH;
    int E = in_sizes[1] / 2;
    if (N > NNODES) N = NNODES;
    if (E > NEDGES) E = NEDGES;
    int NB = (N + SCAN_B - 1) / SCAN_B;

    static cudaStream_t s_aux = nullptr;
    static cudaEvent_t ev_fork = nullptr, ev_join = nullptr;
    if (s_aux == nullptr) {
        cudaStreamCreateWithFlags(&s_aux, cudaStreamNonBlocking);
        cudaEventCreateWithFlags(&ev_fork, cudaEventDisableTiming);
        cudaEventCreateWithFlags(&ev_join, cudaEventDisableTiming);
    }

    k_zero<<<(N + 255) / 256, 256>>>(N);
    cudaEventRecord(ev_fork, 0);
    cudaStreamWaitEvent(s_aux, ev_fork, 0);

    // branch A (main stream): GEMM + logits
    k_proj<<<(N + 63) / 64, 256>>>(x, W, att_s, att_d, N);

    // branch B (aux stream): CSR build
    k_hist<<<(E + 255) / 256, 256, 0, s_aux>>>(ei, E);
    k_scan<<<NB, 256, 0, s_aux>>>(N);
    {
        int half = (E + 1) / 2;
        k_scatter<<<(half + 255) / 256, 256, 0, s_aux>>>(ei, E);
    }
    cudaEventRecord(ev_join, s_aux);
    cudaStreamWaitEvent(0, ev_join, 0);

    int nblk = (N + 3) / 4;
    if (nblk > 4096) nblk = 4096;
    k_agg<<<nblk, 128>>>(out, bias, N);
}

// round 17
// speedup vs baseline: 1.5141x; 1.0195x over previous
#include <cuda_runtime.h>
#include <cuda_fp16.h>
#include <math.h>

#define NNODES 50000
#define NEDGES 1600000
#define INCH   128
#define HEADS  4
#define OUTC   128
#define NEG_SLOPE 0.2f
#define SCAN_B 1024

// Scratch (static device globals; no allocation allowed)
__device__ __half2 g_hb[NNODES * OUTC / 2];   // projected features, fp16x2 [N,64]
__device__ float g_as[NNODES * HEADS];        // a_src [N,4]
__device__ float g_ad[NNODES * HEADS];        // a_dst [N,4]
__device__ int   g_cnt[NNODES];               // in-degree (w/o self loop)
__device__ int   g_off[NNODES];               // CSR offsets (exclusive scan)
__device__ int   g_pos[NEDGES];               // rank of edge within its dst bucket
__device__ int   g_csr_src[NEDGES];           // src node per CSR slot

__device__ __forceinline__ float leaky(float v) {
    return v > 0.0f ? v : NEG_SLOPE * v;
}
__device__ __forceinline__ float4 expleaky4(float4 a, float4 b) {
    float4 r;
    r.x = __expf(leaky(a.x + b.x)); r.y = __expf(leaky(a.y + b.y));
    r.z = __expf(leaky(a.z + b.z)); r.w = __expf(leaky(a.w + b.w));
    return r;
}
__device__ __forceinline__ float sel4(float4 v, int h) {
    return h == 0 ? v.x : h == 1 ? v.y : h == 2 ? v.z : v.w;
}

// packed fp32x2 helpers (FFMA2 only reachable via PTX)
__device__ __forceinline__ unsigned long long pack2(float a, float b) {
    unsigned long long r;
    asm("mov.b64 %0, {%1, %2};" : "=l"(r) : "f"(a), "f"(b));
    return r;
}
__device__ __forceinline__ unsigned long long dup2(float a) {
    unsigned long long r;
    asm("mov.b64 %0, {%1, %1};" : "=l"(r) : "f"(a));
    return r;
}
__device__ __forceinline__ void fma2(unsigned long long& d, unsigned long long a,
                                     unsigned long long b) {
    asm("fma.rn.f32x2 %0, %1, %2, %0;" : "+l"(d) : "l"(a), "l"(b));
}
__device__ __forceinline__ void unpack2(unsigned long long v, float& lo, float& hi) {
    asm("mov.b64 {%0, %1}, %2;" : "=f"(lo), "=f"(hi) : "l"(v));
}

// ---------------------------------------------------------------------------
__global__ void k_zero(int N) {
    int i = blockIdx.x * blockDim.x + threadIdx.x;
    if (i < N) g_cnt[i] = 0;
}

// ---------------------------------------------------------------------------
// Degree histogram; atomic return value = edge's rank in its dst bucket.
// ---------------------------------------------------------------------------
__global__ void k_hist(const int* __restrict__ ei, int E) {
    int e = blockIdx.x * blockDim.x + threadIdx.x;
    if (e < E) g_pos[e] = atomicAdd(&g_cnt[ei[E + e]], 1);
}

// ---------------------------------------------------------------------------
// Projection + logits (GEMM only). Block = 256 threads = 8 warps; each warp
// computes 8 nodes x 128 cols.
// ---------------------------------------------------------------------------
__global__ void k_proj(const float* __restrict__ x, const float* __restrict__ W,
                       const float* __restrict__ att_s, const float* __restrict__ att_d,
                       int N) {
    __shared__ float xs[64][INCH];  // 32 KB
    int t = threadIdx.x;
    int n0 = blockIdx.x * 64;
    int nvalid = min(64, N - n0);

    for (int i = t * 4; i < 64 * INCH; i += 256 * 4) {
        float4 v = make_float4(0.f, 0.f, 0.f, 0.f);
        if (i < nvalid * INCH) v = *(const float4*)&x[(long long)n0 * INCH + i];
        *(float4*)&xs[0][i] = v;
    }
    __syncthreads();

    int warp = t >> 5;
    int lane = t & 31;
    int nb = warp * 8;

    unsigned long long a01[8], a23[8];
#pragma unroll
    for (int j = 0; j < 8; j++) { a01[j] = 0ull; a23[j] = 0ull; }

#pragma unroll 4
    for (int k = 0; k < INCH; k++) {
        float4 w4 = *(const float4*)&W[k * OUTC + lane * 4];
        unsigned long long w01 = pack2(w4.x, w4.y);
        unsigned long long w23 = pack2(w4.z, w4.w);
#pragma unroll
        for (int j = 0; j < 8; j++) {
            unsigned long long xx = dup2(xs[nb + j][k]);
            fma2(a01[j], w01, xx);
            fma2(a23[j], w23, xx);
        }
    }

    float4 s4 = *(const float4*)&att_s[lane * 4];
    float4 d4 = *(const float4*)&att_d[lane * 4];

#pragma unroll
    for (int j = 0; j < 8; j++) {
        int n = n0 + nb + j;
        float4 acc;
        unpack2(a01[j], acc.x, acc.y);
        unpack2(a23[j], acc.z, acc.w);
        if (n < N) {
            __half2 p0 = __float22half2_rn(make_float2(acc.x, acc.y));
            __half2 p1 = __float22half2_rn(make_float2(acc.z, acc.w));
            uint2 p;
            p.x = *(unsigned int*)&p0;
            p.y = *(unsigned int*)&p1;
            *(uint2*)&g_hb[(long long)n * (OUTC / 2) + lane * 2] = p;
        }

        float vs = acc.x * s4.x + acc.y * s4.y + acc.z * s4.z + acc.w * s4.w;
        float vd = acc.x * d4.x + acc.y * d4.y + acc.z * d4.z + acc.w * d4.w;
#pragma unroll
        for (int o = 4; o > 0; o >>= 1) {
            vs += __shfl_down_sync(0xffffffffu, vs, o);
            vd += __shfl_down_sync(0xffffffffu, vd, o);
        }
        if ((lane & 7) == 0 && n < N) {
            int h = lane >> 3;
            g_as[n * HEADS + h] = vs;
            g_ad[n * HEADS + h] = vd;
        }
    }
}

// ---------------------------------------------------------------------------
// Single-kernel exclusive scan; base-sum loop vectorized with int4
// (g_cnt 16B-aligned; pre is a multiple of 1024 or N=50000, both /4).
// ---------------------------------------------------------------------------
__global__ void k_scan(int N) {
    int t = threadIdx.x;
    int b = blockIdx.x;
    __shared__ int sh[256];

    int pre = b * SCAN_B;
    if (pre > N) pre = N;
    int part = 0;
    for (int i = t * 4; i < pre; i += 256 * 4) {
        int4 c4 = *(const int4*)&g_cnt[i];
        part += c4.x + c4.y + c4.z + c4.w;
    }
    sh[t] = part;
    __syncthreads();
#pragma unroll
    for (int o = 128; o > 0; o >>= 1) {
        if (t < o) sh[t] += sh[t + o];
        __syncthreads();
    }
    int base = sh[0];
    __syncthreads();

    int i0 = b * SCAN_B + t * 4;
    int v[4];
    int s = 0;
#pragma unroll
    for (int j = 0; j < 4; j++) {
        v[j] = (i0 + j < N) ? g_cnt[i0 + j] : 0;
        s += v[j];
    }
    sh[t] = s;
    __syncthreads();
    for (int o = 1; o < 256; o <<= 1) {
        int u = (t >= o) ? sh[t - o] : 0;
        __syncthreads();
        sh[t] += u;
        __syncthreads();
    }
    int run = base + ((t == 0) ? 0 : sh[t - 1]);
#pragma unroll
    for (int j = 0; j < 4; j++) {
        if (i0 + j < N) g_off[i0 + j] = run;
        run += v[j];
    }
}

// ---------------------------------------------------------------------------
// Atomic-free scatter, 2 edges per thread (int2 loads on both rows).
// ---------------------------------------------------------------------------
__global__ void k_scatter(const int* __restrict__ ei, int E) {
    int i = blockIdx.x * blockDim.x + threadIdx.x;
    int e = i * 2;
    if (e + 1 < E) {
        int2 s2 = *(const int2*)&ei[e];
        int2 d2 = *(const int2*)&ei[E + e];
        int2 p2 = *(const int2*)&g_pos[e];
        g_csr_src[__ldg(&g_off[d2.x]) + p2.x] = s2.x;
        g_csr_src[__ldg(&g_off[d2.y]) + p2.y] = s2.y;
    } else if (e < E) {
        int s = ei[e];
        int d = ei[E + e];
        g_csr_src[__ldg(&g_off[d]) + g_pos[e]] = s;
    }
}

// ---------------------------------------------------------------------------
// Fused softmax + weighted aggregate + bias + ELU. WARP per destination node,
// grid-stride over nodes for load balance. Block = 128 threads (4 warps).
// Structure locked at the proven round-14 configuration.
// ---------------------------------------------------------------------------
__global__ void k_agg(float* __restrict__ out, const float* __restrict__ bias, int N) {
    int warp = threadIdx.x >> 5;  // 4 warps/block
    int lane = threadIdx.x & 31;
    int head = lane >> 3;

    __shared__ float s_w[4][32][HEADS];  // 2 KB

    float4 b4 = *(const float4*)&bias[lane * 4];
    int nstride = gridDim.x * 4;

    for (int d = blockIdx.x * 4 + warp; d < N; d += nstride) {
        int start = g_off[d];
        int deg = g_cnt[d];

        float4 ad4 = *(const float4*)&g_ad[d * HEADS];
        float4 asd = *(const float4*)&g_as[d * HEADS];
        float4 wself = expleaky4(asd, ad4);

        // self-loop
        float4 den = (lane == 0) ? wself : make_float4(0.f, 0.f, 0.f, 0.f);
        float wts = sel4(wself, head);
        const __half2* hrow = &g_hb[(long long)d * (OUTC / 2) + lane * 2];
        float2 f0 = __half22float2(hrow[0]);
        float2 f1 = __half22float2(hrow[1]);
        float4 acc;
        acc.x = wts * f0.x; acc.y = wts * f0.y;
        acc.z = wts * f1.x; acc.w = wts * f1.y;

        for (int base = 0; base < deg; base += 32) {
            int m = min(32, deg - base);
            int s = 0;
            float4 w = make_float4(0.f, 0.f, 0.f, 0.f);
            if (lane < m) {
                s = g_csr_src[start + base + lane];
                float4 as4 = *(const float4*)&g_as[s * HEADS];
                w = expleaky4(as4, ad4);
                den.x += w.x; den.y += w.y; den.z += w.z; den.w += w.w;
            }
            *(float4*)&s_w[warp][lane][0] = w;
            __syncwarp();
#pragma unroll 8
            for (int e = 0; e < m; e++) {
                int se = __shfl_sync(0xffffffffu, s, e);
                float wt = s_w[warp][e][head];
                uint2 raw = *(const uint2*)&g_hb[(long long)se * (OUTC / 2) + lane * 2];
                float2 g0 = __half22float2(*(__half2*)&raw.x);
                float2 g1 = __half22float2(*(__half2*)&raw.y);
                acc.x = fmaf(wt, g0.x, acc.x);
                acc.y = fmaf(wt, g0.y, acc.y);
                acc.z = fmaf(wt, g1.x, acc.z);
                acc.w = fmaf(wt, g1.y, acc.w);
            }
            __syncwarp();
        }

        // butterfly reduce denominator
#pragma unroll
        for (int o = 16; o > 0; o >>= 1) {
            den.x += __shfl_xor_sync(0xffffffffu, den.x, o);
            den.y += __shfl_xor_sync(0xffffffffu, den.y, o);
            den.z += __shfl_xor_sync(0xffffffffu, den.z, o);
            den.w += __shfl_xor_sync(0xffffffffu, den.w, o);
        }
        float denv = sel4(den, head) + 1e-16f;

        float4 v;
        v.x = acc.x / denv + b4.x;
        v.y = acc.y / denv + b4.y;
        v.z = acc.z / denv + b4.z;
        v.w = acc.w / denv + b4.w;
        v.x = v.x > 0.f ? v.x : expm1f(v.x);
        v.y = v.y > 0.f ? v.y : expm1f(v.y);
        v.z = v.z > 0.f ? v.z : expm1f(v.z);
        v.w = v.w > 0.f ? v.w : expm1f(v.w);
        *(float4*)&out[(long long)d * OUTC + lane * 4] = v;
    }
}

// ---------------------------------------------------------------------------
// Launch DAG (graph-capture fork/join):
//   main:  proj(GEMM) ──────────────────────────┬─ agg
//   aux:   zero → hist → scan → scatter ────────┘
// proj needs nothing from the aux branch, so it starts at t=0.
// Streams/events created lazily on the first (non-captured) correctness call.
// ---------------------------------------------------------------------------
extern "C" void kernel_launch(void* const* d_in, const int* in_sizes, int n_in,
                              void* d_out, int out_size) {
    const float* x = (const float*)d_in[0];
    const int* ei = (const int*)d_in[1];   // int32 (jax downcasts int64 w/o x64)
    const float* W = (const float*)d_in[2];
    const float* att_s = (const float*)d_in[3];
    const float* att_d = (const float*)d_in[4];
    const float* bias = (const float*)d_in[5];
    float* out = (float*)d_out;

    int N = in_sizes[0] / INCH;
    int E = in_sizes[1] / 2;
    if (N > NNODES) N = NNODES;
    if (E > NEDGES) E = NEDGES;
    int NB = (N + SCAN_B - 1) / SCAN_B;

    static cudaStream_t s_aux = nullptr;
    static cudaEvent_t ev_fork = nullptr, ev_join = nullptr;
    if (s_aux == nullptr) {
        cudaStreamCreateWithFlags(&s_aux, cudaStreamNonBlocking);
        cudaEventCreateWithFlags(&ev_fork, cudaEventDisableTiming);
        cudaEventCreateWithFlags(&ev_join, cudaEventDisableTiming);
    }

    // fork: aux branch must be ordered after anything already on stream 0
    cudaEventRecord(ev_fork, 0);
    cudaStreamWaitEvent(s_aux, ev_fork, 0);

    // branch A (main stream): GEMM + logits — starts immediately
    k_proj<<<(N + 63) / 64, 256>>>(x, W, att_s, att_d, N);

    // branch B (aux stream): CSR build
    k_zero<<<(N + 255) / 256, 256, 0, s_aux>>>(N);
    k_hist<<<(E + 255) / 256, 256, 0, s_aux>>>(ei, E);
    k_scan<<<NB, 256, 0, s_aux>>>(N);
    {
        int half = (E + 1) / 2;
        k_scatter<<<(half + 255) / 256, 256, 0, s_aux>>>(ei, E);
    }
    cudaEventRecord(ev_join, s_aux);
    cudaStreamWaitEvent(0, ev_join, 0);

    int nblk = (N + 3) / 4;
    if (nblk > 4096) nblk = 4096;
    k_agg<<<nblk, 128>>>(out, bias, N);
}